// round 8
// baseline (speedup 1.0000x reference)
#include <cuda_runtime.h>
#include <cuda_bf16.h>
#include <cfloat>
#include <math.h>

// ---------------- problem constants ----------------
#define N_NODES   20000
#define N_EDGES   160000
#define N_IN      300
#define NHID      128
#define HEADS     4
#define NOUT      768
#define NUM_GRAPHS 128

typedef unsigned long long ull;

// ---------------- scratch ----------------
__device__ float g_h0[N_NODES * NHID];
__device__ float g_f1[N_NODES * HEADS * NHID];
__device__ float g_o1[N_NODES * HEADS * NHID];
__device__ float g_f2[N_NODES * NHID];
__device__ float g_o2[N_NODES * NHID];
__device__ float g_aldot[N_NODES * HEADS];
__device__ float g_ardot[N_NODES * HEADS];
__device__ int   g_deg[N_NODES];
__device__ int   g_rowptr[N_NODES + 1];
__device__ int   g_cursor[N_NODES];
__device__ int   g_esrc[N_EDGES];
__device__ float g_pool[NUM_GRAPHS * NHID];

// ---------------- tf32 helpers ----------------
__device__ __forceinline__ unsigned f2tf32(float f) {
    unsigned u;
    asm("cvt.rna.tf32.f32 %0, %1;" : "=r"(u) : "f"(f));
    return u;
}
__device__ __forceinline__ void mma_tf32(float& d0, float& d1, float& d2, float& d3,
                                         unsigned a0, unsigned a1, unsigned a2, unsigned a3,
                                         unsigned b0, unsigned b1) {
    asm("mma.sync.aligned.m16n8k8.row.col.f32.tf32.tf32.f32 "
        "{%0,%1,%2,%3}, {%4,%5,%6,%7}, {%8,%9}, {%0,%1,%2,%3};"
        : "+f"(d0), "+f"(d1), "+f"(d2), "+f"(d3)
        : "r"(a0), "r"(a1), "r"(a2), "r"(a3), "r"(b0), "r"(b1));
}

__device__ __forceinline__ float dot4(float4 a, float4 b) {
    return a.x * b.x + a.y * b.y + a.z * b.z + a.w * b.w;
}

// ---------------- CSR build ----------------
__global__ void zero_int_kernel(int* p, int n) {
    int i = blockIdx.x * blockDim.x + threadIdx.x;
    if (i < n) p[i] = 0;
}

__global__ void hist_kernel(const int* __restrict__ dst, int* __restrict__ deg, int E) {
    int i = blockIdx.x * blockDim.x + threadIdx.x;
    if (i < E) atomicAdd(&deg[dst[i]], 1);
}

__global__ void scan_kernel(const int* __restrict__ deg, int* __restrict__ rowptr,
                            int* __restrict__ cursor) {
    __shared__ int sh[1024];
    const int PER = 20;
    int tid = threadIdx.x;
    int base = tid * PER;
    int loc[PER];
    int s = 0;
    #pragma unroll
    for (int i = 0; i < PER; i++) {
        int idx = base + i;
        int v = (idx < N_NODES) ? deg[idx] : 0;
        loc[i] = s;
        s += v;
    }
    sh[tid] = s;
    __syncthreads();
    #pragma unroll
    for (int off = 1; off < 1024; off <<= 1) {
        int t = (tid >= off) ? sh[tid - off] : 0;
        __syncthreads();
        sh[tid] += t;
        __syncthreads();
    }
    int prev = (tid > 0) ? sh[tid - 1] : 0;
    #pragma unroll
    for (int i = 0; i < PER; i++) {
        int idx = base + i;
        if (idx < N_NODES) {
            int v = prev + loc[i];
            rowptr[idx] = v;
            cursor[idx] = v;
        }
    }
    if (tid == 1023) rowptr[N_NODES] = sh[1023];
}

__global__ void scatter_kernel(const int* __restrict__ src, const int* __restrict__ dst,
                               int* __restrict__ cursor, int* __restrict__ esrc, int E) {
    int i = blockIdx.x * blockDim.x + threadIdx.x;
    if (i < E) {
        int d = dst[i];
        int p = atomicAdd(&cursor[d], 1);
        esrc[p] = src[i];
    }
}

// ---------------- tf32 tensor-core GEMM (unchanged control) ----------------
__global__ __launch_bounds__(256, 2)
void gemm_tf32_kernel(const float* __restrict__ A, const float* __restrict__ B,
                      const float* __restrict__ bias, float* __restrict__ C,
                      int M, int N, int K, float slope, int act) {
    const int BM = 128, BK = 16;
    const int ASTR = 136;
    __shared__ unsigned As[BK * ASTR];
    __shared__ unsigned Bs[2 * 16 * 33 * 2];

    int tid = threadIdx.x;
    int lane = tid & 31;
    int wid = tid >> 5;
    int warpM = wid >> 2;
    int warpN = wid & 3;
    int bm = blockIdx.y * BM, bn = blockIdx.x * 128;
    int g = lane >> 2, c = lane & 3;

    float acc[4][4][4];
    #pragma unroll
    for (int mi = 0; mi < 4; mi++)
        #pragma unroll
        for (int ni = 0; ni < 4; ni++)
            #pragma unroll
            for (int r = 0; r < 4; r++) acc[mi][ni][r] = 0.f;

    int la_m = tid >> 1;
    int la_k = (tid & 1) * 8;
    int gmA = bm + la_m;
    int lbk = tid >> 4;
    int lbn = (tid & 15) * 8;
    int b_kb = lbk >> 3;
    int b_c = lbk & 3;
    int b_half = (lbk & 7) >> 2;
    int b_nb = tid & 15;

    for (int k0 = 0; k0 < K; k0 += BK) {
        #pragma unroll
        for (int gg = 0; gg < 8; gg += 4) {
            int kk = la_k + gg;
            int gk = k0 + kk;
            float4 v = make_float4(0.f, 0.f, 0.f, 0.f);
            if (gmA < M && gk < K)
                v = *reinterpret_cast<const float4*>(&A[(size_t)gmA * K + gk]);
            As[(kk + 0) * ASTR + la_m] = f2tf32(v.x);
            As[(kk + 1) * ASTR + la_m] = f2tf32(v.y);
            As[(kk + 2) * ASTR + la_m] = f2tf32(v.z);
            As[(kk + 3) * ASTR + la_m] = f2tf32(v.w);
        }
        {
            int gk = k0 + lbk;
            float4 v0 = make_float4(0.f, 0.f, 0.f, 0.f);
            float4 v1 = make_float4(0.f, 0.f, 0.f, 0.f);
            if (gk < K) {
                v0 = *reinterpret_cast<const float4*>(&B[(size_t)gk * N + bn + lbn]);
                v1 = *reinterpret_cast<const float4*>(&B[(size_t)gk * N + bn + lbn + 4]);
            }
            float vv[8] = {v0.x, v0.y, v0.z, v0.w, v1.x, v1.y, v1.z, v1.w};
            int grp = b_kb * 16 + b_nb;
            #pragma unroll
            for (int j = 0; j < 8; j++) {
                int u = grp * 33 + j * 4 + b_c;
                Bs[2 * u + b_half] = f2tf32(vv[j]);
            }
        }
        __syncthreads();

        #pragma unroll
        for (int kb = 0; kb < 2; kb++) {
            unsigned af[4][4];
            int r0 = (kb * 8 + c) * ASTR;
            int r1 = (kb * 8 + c + 4) * ASTR;
            #pragma unroll
            for (int mi = 0; mi < 4; mi++) {
                int m0 = warpM * 64 + mi * 16;
                af[mi][0] = As[r0 + m0 + g];
                af[mi][1] = As[r0 + m0 + g + 8];
                af[mi][2] = As[r1 + m0 + g];
                af[mi][3] = As[r1 + m0 + g + 8];
            }
            unsigned bf[4][2];
            #pragma unroll
            for (int ni = 0; ni < 4; ni++) {
                int grp = kb * 16 + warpN * 4 + ni;
                uint2 t = *reinterpret_cast<const uint2*>(&Bs[2 * (grp * 33 + lane)]);
                bf[ni][0] = t.x;
                bf[ni][1] = t.y;
            }
            #pragma unroll
            for (int mi = 0; mi < 4; mi++)
                #pragma unroll
                for (int ni = 0; ni < 4; ni++)
                    mma_tf32(acc[mi][ni][0], acc[mi][ni][1], acc[mi][ni][2], acc[mi][ni][3],
                             af[mi][0], af[mi][1], af[mi][2], af[mi][3],
                             bf[ni][0], bf[ni][1]);
        }
        __syncthreads();
    }

    #pragma unroll
    for (int mi = 0; mi < 4; mi++) {
        int row0 = bm + warpM * 64 + mi * 16 + g;
        #pragma unroll
        for (int ni = 0; ni < 4; ni++) {
            int col = bn + warpN * 32 + ni * 8 + c * 2;
            float bv0 = bias ? bias[col] : 0.f;
            float bv1 = bias ? bias[col + 1] : 0.f;
            if (row0 < M) {
                float x0 = acc[mi][ni][0] + bv0;
                float x1 = acc[mi][ni][1] + bv1;
                if (act) {
                    x0 = x0 > 0.f ? x0 : slope * x0;
                    x1 = x1 > 0.f ? x1 : slope * x1;
                }
                *reinterpret_cast<float2*>(&C[(size_t)row0 * N + col]) = make_float2(x0, x1);
            }
            int row1 = row0 + 8;
            if (row1 < M) {
                float x2 = acc[mi][ni][2] + bv0;
                float x3 = acc[mi][ni][3] + bv1;
                if (act) {
                    x2 = x2 > 0.f ? x2 : slope * x2;
                    x3 = x3 > 0.f ? x3 : slope * x3;
                }
                *reinterpret_cast<float2*>(&C[(size_t)row1 * N + col]) = make_float2(x2, x3);
            }
        }
    }
}

// ---------------- precompute attention dots ----------------
template<int H>
__global__ void attdot_kernel(const float* __restrict__ feat,
                              const float* __restrict__ attL, const float* __restrict__ attR,
                              float* __restrict__ aldot, float* __restrict__ ardot) {
    int warp = (blockIdx.x * blockDim.x + threadIdx.x) >> 5;
    int lane = threadIdx.x & 31;
    if (warp >= N_NODES * H) return;
    int nid = warp / H, h = warp % H;
    float4 x = reinterpret_cast<const float4*>(feat + ((size_t)nid * H + h) * NHID)[lane];
    float4 aL = reinterpret_cast<const float4*>(attL + h * NHID)[lane];
    float4 aR = reinterpret_cast<const float4*>(attR + h * NHID)[lane];
    float al = dot4(x, aL);
    float ar = dot4(x, aR);
    #pragma unroll
    for (int o = 16; o; o >>= 1) {
        al += __shfl_xor_sync(0xffffffffu, al, o);
        ar += __shfl_xor_sync(0xffffffffu, ar, o);
    }
    if (lane == 0) { aldot[warp] = al; ardot[warp] = ar; }
}

// ---------------- layer-1 aggregation: one warp per node, all 4 heads ----------------
__global__ void agg4_kernel(const float* __restrict__ feat,
                            const float* __restrict__ aldot, const float* __restrict__ ardot,
                            const float* __restrict__ bias,
                            const int* __restrict__ rowptr, const int* __restrict__ esrc,
                            float* __restrict__ out, float out_slope) {
    int warp = (blockIdx.x * blockDim.x + threadIdx.x) >> 5;
    int lane = threadIdx.x & 31;
    if (warp >= N_NODES) return;
    int nid = warp;

    const float4* fi = reinterpret_cast<const float4*>(feat + (size_t)nid * 512);
    float4 xi0 = fi[lane], xi1 = fi[32 + lane], xi2 = fi[64 + lane], xi3 = fi[96 + lane];
    float4 ar4 = reinterpret_cast<const float4*>(ardot)[nid];

    float m0 = -INFINITY, m1 = -INFINITY, m2 = -INFINITY, m3 = -INFINITY;
    float s0 = 0.f, s1 = 0.f, s2 = 0.f, s3 = 0.f;
    float4 acc0 = make_float4(0.f, 0.f, 0.f, 0.f);
    float4 acc1 = acc0, acc2 = acc0, acc3 = acc0;

    int e0 = rowptr[nid], e1 = rowptr[nid + 1];
    for (int e = e0; e < e1; e++) {
        int sn = esrc[e];
        const float4* fj = reinterpret_cast<const float4*>(feat + (size_t)sn * 512);
        float4 xj0 = fj[lane], xj1 = fj[32 + lane], xj2 = fj[64 + lane], xj3 = fj[96 + lane];
        float lg0 = dot4(xi0, xj0);
        float lg1 = dot4(xi1, xj1);
        float lg2 = dot4(xi2, xj2);
        float lg3 = dot4(xi3, xj3);
        #pragma unroll
        for (int o = 16; o; o >>= 1) {
            lg0 += __shfl_xor_sync(0xffffffffu, lg0, o);
            lg1 += __shfl_xor_sync(0xffffffffu, lg1, o);
            lg2 += __shfl_xor_sync(0xffffffffu, lg2, o);
            lg3 += __shfl_xor_sync(0xffffffffu, lg3, o);
        }
        float4 al4 = reinterpret_cast<const float4*>(aldot)[sn];
        float a0 = (al4.x + ar4.x) * (1.f / (1.f + __expf(-lg0)));
        float a1 = (al4.y + ar4.y) * (1.f / (1.f + __expf(-lg1)));
        float a2 = (al4.z + ar4.z) * (1.f / (1.f + __expf(-lg2)));
        float a3 = (al4.w + ar4.w) * (1.f / (1.f + __expf(-lg3)));
        a0 = a0 > 0.f ? a0 : 0.2f * a0;
        a1 = a1 > 0.f ? a1 : 0.2f * a1;
        a2 = a2 > 0.f ? a2 : 0.2f * a2;
        a3 = a3 > 0.f ? a3 : 0.2f * a3;
        // per-head online softmax updates (independent chains)
        {
            float mn = fmaxf(m0, a0), sc = __expf(m0 - mn), w = __expf(a0 - mn);
            s0 = s0 * sc + w;
            acc0.x = acc0.x * sc + w * xj0.x; acc0.y = acc0.y * sc + w * xj0.y;
            acc0.z = acc0.z * sc + w * xj0.z; acc0.w = acc0.w * sc + w * xj0.w;
            m0 = mn;
        }
        {
            float mn = fmaxf(m1, a1), sc = __expf(m1 - mn), w = __expf(a1 - mn);
            s1 = s1 * sc + w;
            acc1.x = acc1.x * sc + w * xj1.x; acc1.y = acc1.y * sc + w * xj1.y;
            acc1.z = acc1.z * sc + w * xj1.z; acc1.w = acc1.w * sc + w * xj1.w;
            m1 = mn;
        }
        {
            float mn = fmaxf(m2, a2), sc = __expf(m2 - mn), w = __expf(a2 - mn);
            s2 = s2 * sc + w;
            acc2.x = acc2.x * sc + w * xj2.x; acc2.y = acc2.y * sc + w * xj2.y;
            acc2.z = acc2.z * sc + w * xj2.z; acc2.w = acc2.w * sc + w * xj2.w;
            m2 = mn;
        }
        {
            float mn = fmaxf(m3, a3), sc = __expf(m3 - mn), w = __expf(a3 - mn);
            s3 = s3 * sc + w;
            acc3.x = acc3.x * sc + w * xj3.x; acc3.y = acc3.y * sc + w * xj3.y;
            acc3.z = acc3.z * sc + w * xj3.z; acc3.w = acc3.w * sc + w * xj3.w;
            m3 = mn;
        }
    }
    float i0 = 1.f / (s0 + 1e-16f), i1 = 1.f / (s1 + 1e-16f);
    float i2 = 1.f / (s2 + 1e-16f), i3 = 1.f / (s3 + 1e-16f);
    float4* po = reinterpret_cast<float4*>(out + (size_t)nid * 512);
    const float4* pb = reinterpret_cast<const float4*>(bias);
    #pragma unroll
    for (int h = 0; h < 4; h++) {
        float4 a = h == 0 ? acc0 : h == 1 ? acc1 : h == 2 ? acc2 : acc3;
        float iv = h == 0 ? i0 : h == 1 ? i1 : h == 2 ? i2 : i3;
        float4 b4 = pb[h * 32 + lane];
        float4 r;
        r.x = a.x * iv + b4.x; r.x = r.x > 0.f ? r.x : out_slope * r.x;
        r.y = a.y * iv + b4.y; r.y = r.y > 0.f ? r.y : out_slope * r.y;
        r.z = a.z * iv + b4.z; r.z = r.z > 0.f ? r.z : out_slope * r.z;
        r.w = a.w * iv + b4.w; r.w = r.w > 0.f ? r.w : out_slope * r.w;
        po[h * 32 + lane] = r;
    }
}

// ---------------- layer-2 aggregation: one warp per node, H=1, 4-edge unroll ----------------
__global__ void agg1_kernel(const float* __restrict__ feat,
                            const float* __restrict__ aldot, const float* __restrict__ ardot,
                            const float* __restrict__ bias,
                            const int* __restrict__ rowptr, const int* __restrict__ esrc,
                            float* __restrict__ out, float out_slope) {
    const int C = NHID;
    int warp = (blockIdx.x * blockDim.x + threadIdx.x) >> 5;
    int lane = threadIdx.x & 31;
    if (warp >= N_NODES) return;
    int nid = warp;

    float4 xi = reinterpret_cast<const float4*>(feat + (size_t)nid * C)[lane];
    float ar = ardot[nid];

    float m = -INFINITY, s = 0.f;
    float4 acc = make_float4(0.f, 0.f, 0.f, 0.f);

    int e0 = rowptr[nid], e1 = rowptr[nid + 1];
    int e = e0;
    for (; e + 3 < e1; e += 4) {
        int s0 = esrc[e], s1 = esrc[e + 1], s2 = esrc[e + 2], s3 = esrc[e + 3];
        float4 xj0 = reinterpret_cast<const float4*>(feat + (size_t)s0 * C)[lane];
        float4 xj1 = reinterpret_cast<const float4*>(feat + (size_t)s1 * C)[lane];
        float4 xj2 = reinterpret_cast<const float4*>(feat + (size_t)s2 * C)[lane];
        float4 xj3 = reinterpret_cast<const float4*>(feat + (size_t)s3 * C)[lane];
        float lg0 = dot4(xi, xj0), lg1 = dot4(xi, xj1);
        float lg2 = dot4(xi, xj2), lg3 = dot4(xi, xj3);
        #pragma unroll
        for (int o = 16; o; o >>= 1) {
            lg0 += __shfl_xor_sync(0xffffffffu, lg0, o);
            lg1 += __shfl_xor_sync(0xffffffffu, lg1, o);
            lg2 += __shfl_xor_sync(0xffffffffu, lg2, o);
            lg3 += __shfl_xor_sync(0xffffffffu, lg3, o);
        }
        float a0 = (aldot[s0] + ar) * (1.f / (1.f + __expf(-lg0)));
        float a1 = (aldot[s1] + ar) * (1.f / (1.f + __expf(-lg1)));
        float a2 = (aldot[s2] + ar) * (1.f / (1.f + __expf(-lg2)));
        float a3 = (aldot[s3] + ar) * (1.f / (1.f + __expf(-lg3)));
        a0 = a0 > 0.f ? a0 : 0.2f * a0;
        a1 = a1 > 0.f ? a1 : 0.2f * a1;
        a2 = a2 > 0.f ? a2 : 0.2f * a2;
        a3 = a3 > 0.f ? a3 : 0.2f * a3;
        float mx = fmaxf(fmaxf(a0, a1), fmaxf(a2, a3));
        float mn = fmaxf(m, mx);
        float sc = __expf(m - mn);
        float w0 = __expf(a0 - mn), w1 = __expf(a1 - mn);
        float w2 = __expf(a2 - mn), w3 = __expf(a3 - mn);
        s = s * sc + w0 + w1 + w2 + w3;
        acc.x = acc.x * sc + w0 * xj0.x + w1 * xj1.x + w2 * xj2.x + w3 * xj3.x;
        acc.y = acc.y * sc + w0 * xj0.y + w1 * xj1.y + w2 * xj2.y + w3 * xj3.y;
        acc.z = acc.z * sc + w0 * xj0.z + w1 * xj1.z + w2 * xj2.z + w3 * xj3.z;
        acc.w = acc.w * sc + w0 * xj0.w + w1 * xj1.w + w2 * xj2.w + w3 * xj3.w;
        m = mn;
    }
    for (; e < e1; e++) {
        int sn = esrc[e];
        float4 xj = reinterpret_cast<const float4*>(feat + (size_t)sn * C)[lane];
        float lg = dot4(xi, xj);
        #pragma unroll
        for (int o = 16; o; o >>= 1) lg += __shfl_xor_sync(0xffffffffu, lg, o);
        float a = (aldot[sn] + ar) * (1.f / (1.f + __expf(-lg)));
        a = a > 0.f ? a : 0.2f * a;
        float mn = fmaxf(m, a);
        float sc = __expf(m - mn);
        float w = __expf(a - mn);
        s = s * sc + w;
        acc.x = acc.x * sc + w * xj.x;
        acc.y = acc.y * sc + w * xj.y;
        acc.z = acc.z * sc + w * xj.z;
        acc.w = acc.w * sc + w * xj.w;
        m = mn;
    }
    float inv = 1.f / (s + 1e-16f);
    float4 b4 = reinterpret_cast<const float4*>(bias)[lane];
    float4 r;
    r.x = acc.x * inv + b4.x; r.x = r.x > 0.f ? r.x : out_slope * r.x;
    r.y = acc.y * inv + b4.y; r.y = r.y > 0.f ? r.y : out_slope * r.y;
    r.z = acc.z * inv + b4.z; r.z = r.z > 0.f ? r.z : out_slope * r.z;
    r.w = acc.w * inv + b4.w; r.w = r.w > 0.f ? r.w : out_slope * r.w;
    reinterpret_cast<float4*>(out + (size_t)nid * C)[lane] = r;
}

// ---------------- graph pooling ----------------
__global__ void pool_init_kernel(float* pool) {
    int i = blockIdx.x * blockDim.x + threadIdx.x;
    if (i < NUM_GRAPHS * NHID) pool[i] = -FLT_MAX;
}

__device__ __forceinline__ void atomicMaxF(float* a, float v) {
    if (v >= 0.f) atomicMax((int*)a, __float_as_int(v));
    else          atomicMin((unsigned int*)a, __float_as_uint(v));
}

__global__ void pool_max_kernel(const float* __restrict__ x, const int* __restrict__ batch,
                                float* __restrict__ pool) {
    int i = blockIdx.x * blockDim.x + threadIdx.x;
    if (i >= N_NODES * NHID) return;
    int n = i / NHID, c = i % NHID;
    atomicMaxF(&pool[batch[n] * NHID + c], x[i]);
}

// ---------------- launch ----------------
static inline float* symf(const void* sym) {
    void* p = nullptr; cudaGetSymbolAddress(&p, sym); return (float*)p;
}
static inline int* symi(const void* sym) {
    void* p = nullptr; cudaGetSymbolAddress(&p, sym); return (int*)p;
}

extern "C" void kernel_launch(void* const* d_in, const int* in_sizes, int n_in,
                              void* d_out, int out_size) {
    const float* x      = (const float*)d_in[0];
    const int*   eidx   = (const int*)  d_in[1];
    const int*   batch  = (const int*)  d_in[2];
    const float* fc1_w  = (const float*)d_in[3];
    const float* fc1_b  = (const float*)d_in[4];
    const float* w1     = (const float*)d_in[5];
    const float* att_l1 = (const float*)d_in[6];
    const float* att_r1 = (const float*)d_in[7];
    const float* b1     = (const float*)d_in[8];
    const float* w2     = (const float*)d_in[9];
    const float* att_l2 = (const float*)d_in[10];
    const float* att_r2 = (const float*)d_in[11];
    const float* b2     = (const float*)d_in[12];
    const float* fc2_w  = (const float*)d_in[13];
    const float* fc2_b  = (const float*)d_in[14];
    float* out = (float*)d_out;

    const int* e_src = eidx;
    const int* e_dst = eidx + N_EDGES;

    float* h0 = symf(g_h0); float* f1 = symf(g_f1); float* o1 = symf(g_o1);
    float* f2 = symf(g_f2); float* o2 = symf(g_o2); float* pool = symf(g_pool);
    float* aldot = symf(g_aldot); float* ardot = symf(g_ardot);
    int* deg = symi(g_deg); int* rowptr = symi(g_rowptr);
    int* cursor = symi(g_cursor); int* esrc = symi(g_esrc);

    zero_int_kernel<<<(N_NODES + 255) / 256, 256>>>(deg, N_NODES);                     // 0
    hist_kernel<<<(N_EDGES + 255) / 256, 256>>>(e_dst, deg, N_EDGES);                  // 1

    // GEMM1: h0 = leaky(x @ fc1_w + fc1_b)
    {
        dim3 grid(NHID / 128, (N_NODES + 127) / 128);
        gemm_tf32_kernel<<<grid, 256>>>(x, fc1_w, fc1_b, h0, N_NODES, NHID, N_IN, 0.01f, 1); // 2
    }
    // GEMM2: f1 = h0 @ w1   (profiled slot 3, control)
    {
        dim3 grid(HEADS * NHID / 128, (N_NODES + 127) / 128);
        gemm_tf32_kernel<<<grid, 256>>>(h0, w1, nullptr, f1, N_NODES, HEADS * NHID, NHID, 0.f, 0); // 3
    }

    scan_kernel<<<1, 1024>>>(deg, rowptr, cursor);                                     // 4
    scatter_kernel<<<(N_EDGES + 255) / 256, 256>>>(e_src, e_dst, cursor, esrc, N_EDGES); // 5

    {
        int warps = N_NODES * HEADS;
        attdot_kernel<HEADS><<<(warps * 32 + 255) / 256, 256>>>(f1, att_l1, att_r1, aldot, ardot); // 6
    }
    // Aggregation layer 1 (head-vectorized: one warp per node)
    agg4_kernel<<<(N_NODES * 32 + 255) / 256, 256>>>(f1, aldot, ardot, b1,
                                                     rowptr, esrc, o1, 0.01f);         // 7
    // GEMM3: f2 = o1 @ w2
    {
        dim3 grid(NHID / 128, (N_NODES + 127) / 128);
        gemm_tf32_kernel<<<grid, 256>>>(o1, w2, nullptr, f2, N_NODES, NHID, HEADS * NHID, 0.f, 0); // 8
    }
    {
        int warps = N_NODES;
        attdot_kernel<1><<<(warps * 32 + 255) / 256, 256>>>(f2, att_l2, att_r2, aldot, ardot); // 9
    }
    // Aggregation layer 2 (4-edge unroll)
    agg1_kernel<<<(N_NODES * 32 + 255) / 256, 256>>>(f2, aldot, ardot, b2,
                                                     rowptr, esrc, o2, 0.01f);         // 10
    pool_init_kernel<<<(NUM_GRAPHS * NHID + 255) / 256, 256>>>(pool);                  // 11
    pool_max_kernel<<<(N_NODES * NHID + 255) / 256, 256>>>(o2, batch, pool);           // 12

    // GEMM4
    {
        dim3 grid(NOUT / 128, (NUM_GRAPHS + 127) / 128);
        gemm_tf32_kernel<<<grid, 256>>>(pool, fc2_w, fc2_b, out, NUM_GRAPHS, NOUT, NHID, 0.f, 0); // 13
    }
}

// round 9
// speedup vs baseline: 1.1374x; 1.1374x over previous
#include <cuda_runtime.h>
#include <cuda_bf16.h>
#include <cfloat>
#include <math.h>

// ---------------- problem constants ----------------
#define N_NODES   20000
#define N_EDGES   160000
#define N_IN      300
#define NHID      128
#define HEADS     4
#define NOUT      768
#define NUM_GRAPHS 128

typedef unsigned long long ull;

// ---------------- scratch ----------------
__device__ float g_h0[N_NODES * NHID];
__device__ float g_f1[N_NODES * HEADS * NHID];
__device__ float g_o1[N_NODES * HEADS * NHID];
__device__ float g_f2[N_NODES * NHID];
__device__ float g_o2[N_NODES * NHID];
__device__ float g_aldot[N_NODES * HEADS];
__device__ float g_ardot[N_NODES * HEADS];
__device__ int   g_deg[N_NODES];
__device__ int   g_rowptr[N_NODES + 1];
__device__ int   g_cursor[N_NODES];
__device__ int   g_esrc[N_EDGES];
__device__ float g_pool[NUM_GRAPHS * NHID];

// ---------------- tf32 helpers ----------------
__device__ __forceinline__ unsigned f2tf32(float f) {
    unsigned u;
    asm("cvt.rna.tf32.f32 %0, %1;" : "=r"(u) : "f"(f));
    return u;
}
__device__ __forceinline__ void mma_tf32(float& d0, float& d1, float& d2, float& d3,
                                         unsigned a0, unsigned a1, unsigned a2, unsigned a3,
                                         unsigned b0, unsigned b1) {
    asm("mma.sync.aligned.m16n8k8.row.col.f32.tf32.tf32.f32 "
        "{%0,%1,%2,%3}, {%4,%5,%6,%7}, {%8,%9}, {%0,%1,%2,%3};"
        : "+f"(d0), "+f"(d1), "+f"(d2), "+f"(d3)
        : "r"(a0), "r"(a1), "r"(a2), "r"(a3), "r"(b0), "r"(b1));
}

__device__ __forceinline__ float dot4(float4 a, float4 b) {
    return a.x * b.x + a.y * b.y + a.z * b.z + a.w * b.w;
}

// ---------------- CSR build ----------------
__global__ void zero_int_kernel(int* p, int n) {
    int i = blockIdx.x * blockDim.x + threadIdx.x;
    if (i < n) p[i] = 0;
}

__global__ void hist_kernel(const int* __restrict__ dst, int* __restrict__ deg, int E) {
    int i = blockIdx.x * blockDim.x + threadIdx.x;
    if (i < E) atomicAdd(&deg[dst[i]], 1);
}

__global__ void scan_kernel(const int* __restrict__ deg, int* __restrict__ rowptr,
                            int* __restrict__ cursor) {
    __shared__ int sh[1024];
    const int PER = 20;
    int tid = threadIdx.x;
    int base = tid * PER;
    int loc[PER];
    int s = 0;
    #pragma unroll
    for (int i = 0; i < PER; i++) {
        int idx = base + i;
        int v = (idx < N_NODES) ? deg[idx] : 0;
        loc[i] = s;
        s += v;
    }
    sh[tid] = s;
    __syncthreads();
    #pragma unroll
    for (int off = 1; off < 1024; off <<= 1) {
        int t = (tid >= off) ? sh[tid - off] : 0;
        __syncthreads();
        sh[tid] += t;
        __syncthreads();
    }
    int prev = (tid > 0) ? sh[tid - 1] : 0;
    #pragma unroll
    for (int i = 0; i < PER; i++) {
        int idx = base + i;
        if (idx < N_NODES) {
            int v = prev + loc[i];
            rowptr[idx] = v;
            cursor[idx] = v;
        }
    }
    if (tid == 1023) rowptr[N_NODES] = sh[1023];
}

__global__ void scatter_kernel(const int* __restrict__ src, const int* __restrict__ dst,
                               int* __restrict__ cursor, int* __restrict__ esrc, int E) {
    int i = blockIdx.x * blockDim.x + threadIdx.x;
    if (i < E) {
        int d = dst[i];
        int p = atomicAdd(&cursor[d], 1);
        esrc[p] = src[i];
    }
}

// ---------------- tf32 tensor-core GEMM, templated BM (64 or 128) ----------------
// THREADS = 2*BM. Warp tile 64x32; BM=128: 8 warps (2x4); BM=64: 4 warps (1x4).
// A smem [BK][BM+8]; B fragment-permuted (33-float2 groups).
template<int BM>
__global__ __launch_bounds__(2 * BM)
void gemm_tf32_kernel(const float* __restrict__ A, const float* __restrict__ B,
                      const float* __restrict__ bias, float* __restrict__ C,
                      int M, int N, int K, float slope, int act) {
    const int BK = 16;
    const int ASTR = BM + 8;
    const int THREADS = 2 * BM;
    const int BROWS = THREADS / 16;          // B loader rows per pass (16 or 8)
    const int BPASS = 16 / BROWS;            // passes (1 or 2)
    __shared__ unsigned As[BK * ASTR];
    __shared__ unsigned Bs[2 * 16 * 33 * 2];

    int tid = threadIdx.x;
    int lane = tid & 31;
    int wid = tid >> 5;
    int warpM = wid >> 2;                    // 0..1 (always 0 when BM=64)
    int warpN = wid & 3;                     // 0..3
    int bm = blockIdx.y * BM, bn = blockIdx.x * 128;
    int g = lane >> 2, c = lane & 3;

    float acc[4][4][4];
    #pragma unroll
    for (int mi = 0; mi < 4; mi++)
        #pragma unroll
        for (int ni = 0; ni < 4; ni++)
            #pragma unroll
            for (int r = 0; r < 4; r++) acc[mi][ni][r] = 0.f;

    int la_m = tid >> 1;                     // 0..BM-1
    int la_k = (tid & 1) * 8;
    int gmA = bm + la_m;
    int lbn = (tid & 15) * 8;
    int b_nb = tid & 15;

    for (int k0 = 0; k0 < K; k0 += BK) {
        // ---- stage A ----
        #pragma unroll
        for (int gg = 0; gg < 8; gg += 4) {
            int kk = la_k + gg;
            int gk = k0 + kk;
            float4 v = make_float4(0.f, 0.f, 0.f, 0.f);
            if (gmA < M && gk < K)
                v = *reinterpret_cast<const float4*>(&A[(size_t)gmA * K + gk]);
            As[(kk + 0) * ASTR + la_m] = f2tf32(v.x);
            As[(kk + 1) * ASTR + la_m] = f2tf32(v.y);
            As[(kk + 2) * ASTR + la_m] = f2tf32(v.z);
            As[(kk + 3) * ASTR + la_m] = f2tf32(v.w);
        }
        // ---- stage B (fragment-permuted) ----
        #pragma unroll
        for (int pass = 0; pass < BPASS; pass++) {
            int lbk = (tid >> 4) + pass * BROWS;   // 0..15
            int b_kb = lbk >> 3;
            int b_c = lbk & 3;
            int b_half = (lbk & 7) >> 2;
            int gk = k0 + lbk;
            float4 v0 = make_float4(0.f, 0.f, 0.f, 0.f);
            float4 v1 = make_float4(0.f, 0.f, 0.f, 0.f);
            if (gk < K) {
                v0 = *reinterpret_cast<const float4*>(&B[(size_t)gk * N + bn + lbn]);
                v1 = *reinterpret_cast<const float4*>(&B[(size_t)gk * N + bn + lbn + 4]);
            }
            float vv[8] = {v0.x, v0.y, v0.z, v0.w, v1.x, v1.y, v1.z, v1.w};
            int grp = b_kb * 16 + b_nb;
            #pragma unroll
            for (int j = 0; j < 8; j++) {
                int u = grp * 33 + j * 4 + b_c;
                Bs[2 * u + b_half] = f2tf32(vv[j]);
            }
        }
        __syncthreads();

        // ---- compute 2 k8 steps ----
        #pragma unroll
        for (int kb = 0; kb < 2; kb++) {
            unsigned af[4][4];
            int r0 = (kb * 8 + c) * ASTR;
            int r1 = (kb * 8 + c + 4) * ASTR;
            #pragma unroll
            for (int mi = 0; mi < 4; mi++) {
                int m0 = warpM * 64 + mi * 16;
                af[mi][0] = As[r0 + m0 + g];
                af[mi][1] = As[r0 + m0 + g + 8];
                af[mi][2] = As[r1 + m0 + g];
                af[mi][3] = As[r1 + m0 + g + 8];
            }
            unsigned bf[4][2];
            #pragma unroll
            for (int ni = 0; ni < 4; ni++) {
                int grp = kb * 16 + warpN * 4 + ni;
                uint2 t = *reinterpret_cast<const uint2*>(&Bs[2 * (grp * 33 + lane)]);
                bf[ni][0] = t.x;
                bf[ni][1] = t.y;
            }
            #pragma unroll
            for (int mi = 0; mi < 4; mi++)
                #pragma unroll
                for (int ni = 0; ni < 4; ni++)
                    mma_tf32(acc[mi][ni][0], acc[mi][ni][1], acc[mi][ni][2], acc[mi][ni][3],
                             af[mi][0], af[mi][1], af[mi][2], af[mi][3],
                             bf[ni][0], bf[ni][1]);
        }
        __syncthreads();
    }

    // ---- epilogue ----
    #pragma unroll
    for (int mi = 0; mi < 4; mi++) {
        int row0 = bm + warpM * 64 + mi * 16 + g;
        #pragma unroll
        for (int ni = 0; ni < 4; ni++) {
            int col = bn + warpN * 32 + ni * 8 + c * 2;
            float bv0 = bias ? bias[col] : 0.f;
            float bv1 = bias ? bias[col + 1] : 0.f;
            if (row0 < M) {
                float x0 = acc[mi][ni][0] + bv0;
                float x1 = acc[mi][ni][1] + bv1;
                if (act) {
                    x0 = x0 > 0.f ? x0 : slope * x0;
                    x1 = x1 > 0.f ? x1 : slope * x1;
                }
                *reinterpret_cast<float2*>(&C[(size_t)row0 * N + col]) = make_float2(x0, x1);
            }
            int row1 = row0 + 8;
            if (row1 < M) {
                float x2 = acc[mi][ni][2] + bv0;
                float x3 = acc[mi][ni][3] + bv1;
                if (act) {
                    x2 = x2 > 0.f ? x2 : slope * x2;
                    x3 = x3 > 0.f ? x3 : slope * x3;
                }
                *reinterpret_cast<float2*>(&C[(size_t)row1 * N + col]) = make_float2(x2, x3);
            }
        }
    }
}

// ---------------- precompute attention dots ----------------
template<int H>
__global__ void attdot_kernel(const float* __restrict__ feat,
                              const float* __restrict__ attL, const float* __restrict__ attR,
                              float* __restrict__ aldot, float* __restrict__ ardot) {
    int warp = (blockIdx.x * blockDim.x + threadIdx.x) >> 5;
    int lane = threadIdx.x & 31;
    if (warp >= N_NODES * H) return;
    int nid = warp / H, h = warp % H;
    float4 x = reinterpret_cast<const float4*>(feat + ((size_t)nid * H + h) * NHID)[lane];
    float4 aL = reinterpret_cast<const float4*>(attL + h * NHID)[lane];
    float4 aR = reinterpret_cast<const float4*>(attR + h * NHID)[lane];
    float al = dot4(x, aL);
    float ar = dot4(x, aR);
    #pragma unroll
    for (int o = 16; o; o >>= 1) {
        al += __shfl_xor_sync(0xffffffffu, al, o);
        ar += __shfl_xor_sync(0xffffffffu, ar, o);
    }
    if (lane == 0) { aldot[warp] = al; ardot[warp] = ar; }
}

// ---------------- SuperGAT aggregation (R7-proven: one warp per (node, head)) ----------------
template<int H>
__global__ void agg_kernel(const float* __restrict__ feat,
                           const float* __restrict__ aldot, const float* __restrict__ ardot,
                           const float* __restrict__ bias,
                           const int* __restrict__ rowptr, const int* __restrict__ esrc,
                           float* __restrict__ out, float out_slope) {
    const int C = NHID;
    int warp = (blockIdx.x * blockDim.x + threadIdx.x) >> 5;
    int lane = threadIdx.x & 31;
    if (warp >= N_NODES * H) return;
    int nid = warp / H;
    int h   = warp % H;

    float4 xi = reinterpret_cast<const float4*>(feat + ((size_t)nid * H + h) * C)[lane];
    float ar = ardot[warp];

    float m = -INFINITY, s = 0.f;
    float4 acc = make_float4(0.f, 0.f, 0.f, 0.f);

    int e0 = rowptr[nid], e1 = rowptr[nid + 1];
    int e = e0;
    for (; e + 1 < e1; e += 2) {
        int s1 = esrc[e], s2 = esrc[e + 1];
        float4 xj1 = reinterpret_cast<const float4*>(feat + ((size_t)s1 * H + h) * C)[lane];
        float4 xj2 = reinterpret_cast<const float4*>(feat + ((size_t)s2 * H + h) * C)[lane];
        float lg1 = dot4(xi, xj1);
        float lg2 = dot4(xi, xj2);
        #pragma unroll
        for (int o = 16; o; o >>= 1) {
            lg1 += __shfl_xor_sync(0xffffffffu, lg1, o);
            lg2 += __shfl_xor_sync(0xffffffffu, lg2, o);
        }
        float al1 = aldot[s1 * H + h], al2 = aldot[s2 * H + h];
        float a1 = (al1 + ar) * (1.f / (1.f + __expf(-lg1)));
        float a2 = (al2 + ar) * (1.f / (1.f + __expf(-lg2)));
        a1 = a1 > 0.f ? a1 : 0.2f * a1;
        a2 = a2 > 0.f ? a2 : 0.2f * a2;
        float mn = fmaxf(m, fmaxf(a1, a2));
        float scale = __expf(m - mn);
        float w1 = __expf(a1 - mn), w2 = __expf(a2 - mn);
        s = s * scale + w1 + w2;
        acc.x = acc.x * scale + w1 * xj1.x + w2 * xj2.x;
        acc.y = acc.y * scale + w1 * xj1.y + w2 * xj2.y;
        acc.z = acc.z * scale + w1 * xj1.z + w2 * xj2.z;
        acc.w = acc.w * scale + w1 * xj1.w + w2 * xj2.w;
        m = mn;
    }
    for (; e < e1; e++) {
        int sn = esrc[e];
        float4 xj = reinterpret_cast<const float4*>(feat + ((size_t)sn * H + h) * C)[lane];
        float lg = dot4(xi, xj);
        #pragma unroll
        for (int o = 16; o; o >>= 1) lg += __shfl_xor_sync(0xffffffffu, lg, o);
        float al = aldot[sn * H + h];
        float a = (al + ar) * (1.f / (1.f + __expf(-lg)));
        a = a > 0.f ? a : 0.2f * a;
        float mn = fmaxf(m, a);
        float scale = __expf(m - mn);
        float w = __expf(a - mn);
        s = s * scale + w;
        acc.x = acc.x * scale + w * xj.x;
        acc.y = acc.y * scale + w * xj.y;
        acc.z = acc.z * scale + w * xj.z;
        acc.w = acc.w * scale + w * xj.w;
        m = mn;
    }
    float inv = 1.f / (s + 1e-16f);
    float4 b4 = reinterpret_cast<const float4*>(bias + h * C)[lane];
    float4 r;
    r.x = acc.x * inv + b4.x; r.x = r.x > 0.f ? r.x : out_slope * r.x;
    r.y = acc.y * inv + b4.y; r.y = r.y > 0.f ? r.y : out_slope * r.y;
    r.z = acc.z * inv + b4.z; r.z = r.z > 0.f ? r.z : out_slope * r.z;
    r.w = acc.w * inv + b4.w; r.w = r.w > 0.f ? r.w : out_slope * r.w;
    reinterpret_cast<float4*>(out + ((size_t)nid * H + h) * C)[lane] = r;
}

// ---------------- graph pooling ----------------
__global__ void pool_init_kernel(float* pool) {
    int i = blockIdx.x * blockDim.x + threadIdx.x;
    if (i < NUM_GRAPHS * NHID) pool[i] = -FLT_MAX;
}

__device__ __forceinline__ void atomicMaxF(float* a, float v) {
    if (v >= 0.f) atomicMax((int*)a, __float_as_int(v));
    else          atomicMin((unsigned int*)a, __float_as_uint(v));
}

__global__ void pool_max_kernel(const float* __restrict__ x, const int* __restrict__ batch,
                                float* __restrict__ pool) {
    int i = blockIdx.x * blockDim.x + threadIdx.x;
    if (i >= N_NODES * NHID) return;
    int n = i / NHID, c = i % NHID;
    atomicMaxF(&pool[batch[n] * NHID + c], x[i]);
}

// ---------------- launch ----------------
static inline float* symf(const void* sym) {
    void* p = nullptr; cudaGetSymbolAddress(&p, sym); return (float*)p;
}
static inline int* symi(const void* sym) {
    void* p = nullptr; cudaGetSymbolAddress(&p, sym); return (int*)p;
}

extern "C" void kernel_launch(void* const* d_in, const int* in_sizes, int n_in,
                              void* d_out, int out_size) {
    const float* x      = (const float*)d_in[0];
    const int*   eidx   = (const int*)  d_in[1];
    const int*   batch  = (const int*)  d_in[2];
    const float* fc1_w  = (const float*)d_in[3];
    const float* fc1_b  = (const float*)d_in[4];
    const float* w1     = (const float*)d_in[5];
    const float* att_l1 = (const float*)d_in[6];
    const float* att_r1 = (const float*)d_in[7];
    const float* b1     = (const float*)d_in[8];
    const float* w2     = (const float*)d_in[9];
    const float* att_l2 = (const float*)d_in[10];
    const float* att_r2 = (const float*)d_in[11];
    const float* b2     = (const float*)d_in[12];
    const float* fc2_w  = (const float*)d_in[13];
    const float* fc2_b  = (const float*)d_in[14];
    float* out = (float*)d_out;

    const int* e_src = eidx;
    const int* e_dst = eidx + N_EDGES;

    float* h0 = symf(g_h0); float* f1 = symf(g_f1); float* o1 = symf(g_o1);
    float* f2 = symf(g_f2); float* o2 = symf(g_o2); float* pool = symf(g_pool);
    float* aldot = symf(g_aldot); float* ardot = symf(g_ardot);
    int* deg = symi(g_deg); int* rowptr = symi(g_rowptr);
    int* cursor = symi(g_cursor); int* esrc = symi(g_esrc);

    zero_int_kernel<<<(N_NODES + 255) / 256, 256>>>(deg, N_NODES);                     // 0
    hist_kernel<<<(N_EDGES + 255) / 256, 256>>>(e_dst, deg, N_EDGES);                  // 1

    // GEMM1: h0 = leaky(x @ fc1_w + fc1_b)  [20000,300]x[300,128] -> BM=64, 313 blocks
    {
        dim3 grid(NHID / 128, (N_NODES + 63) / 64);
        gemm_tf32_kernel<64><<<grid, 128>>>(x, fc1_w, fc1_b, h0, N_NODES, NHID, N_IN, 0.01f, 1); // 2
    }
    // GEMM2: f1 = h0 @ w1   [20000,128]x[128,512]  (profiled slot 3, control, BM=128)
    {
        dim3 grid(HEADS * NHID / 128, (N_NODES + 127) / 128);
        gemm_tf32_kernel<128><<<grid, 256>>>(h0, w1, nullptr, f1, N_NODES, HEADS * NHID, NHID, 0.f, 0); // 3
    }

    scan_kernel<<<1, 1024>>>(deg, rowptr, cursor);                                     // 4
    scatter_kernel<<<(N_EDGES + 255) / 256, 256>>>(e_src, e_dst, cursor, esrc, N_EDGES); // 5

    {
        int warps = N_NODES * HEADS;
        attdot_kernel<HEADS><<<(warps * 32 + 255) / 256, 256>>>(f1, att_l1, att_r1, aldot, ardot); // 6
    }
    // Aggregation layer 1 (R7 layout: one warp per (node,head))
    {
        int warps = N_NODES * HEADS;
        agg_kernel<HEADS><<<(warps * 32 + 255) / 256, 256>>>(f1, aldot, ardot, b1,
                                                             rowptr, esrc, o1, 0.01f); // 7
    }
    // GEMM3: f2 = o1 @ w2   [20000,512]x[512,128] -> BM=64, 313 blocks
    {
        dim3 grid(NHID / 128, (N_NODES + 63) / 64);
        gemm_tf32_kernel<64><<<grid, 128>>>(o1, w2, nullptr, f2, N_NODES, NHID, HEADS * NHID, 0.f, 0); // 8
    }
    {
        int warps = N_NODES;
        attdot_kernel<1><<<(warps * 32 + 255) / 256, 256>>>(f2, att_l2, att_r2, aldot, ardot); // 9
    }
    // Aggregation layer 2 (R7 layout)
    {
        int warps = N_NODES;
        agg_kernel<1><<<(warps * 32 + 255) / 256, 256>>>(f2, aldot, ardot, b2,
                                                         rowptr, esrc, o2, 0.01f);     // 10
    }
    pool_init_kernel<<<(NUM_GRAPHS * NHID + 255) / 256, 256>>>(pool);                  // 11
    pool_max_kernel<<<(N_NODES * NHID + 255) / 256, 256>>>(o2, batch, pool);           // 12

    // GEMM4: out = pool @ fc2_w + fc2_b   [128,128]x[128,768]  BM=128
    {
        dim3 grid(NOUT / 128, (NUM_GRAPHS + 127) / 128);
        gemm_tf32_kernel<128><<<grid, 256>>>(pool, fc2_w, fc2_b, out, NUM_GRAPHS, NOUT, NHID, 0.f, 0); // 13
    }
}

// round 10
// speedup vs baseline: 1.1506x; 1.0116x over previous
#include <cuda_runtime.h>
#include <cuda_bf16.h>
#include <cfloat>
#include <math.h>

// ---------------- problem constants ----------------
#define N_NODES   20000
#define N_EDGES   160000
#define N_IN      300
#define NHID      128
#define HEADS     4
#define NOUT      768
#define NUM_GRAPHS 128

typedef unsigned long long ull;

// ---------------- scratch ----------------
__device__ float g_h0[N_NODES * NHID];
__device__ float g_f1[N_NODES * HEADS * NHID];
__device__ float g_o1[N_NODES * HEADS * NHID];
__device__ float g_f2[N_NODES * NHID];
__device__ float g_o2[N_NODES * NHID];
__device__ float g_aldot[N_NODES * HEADS];
__device__ float g_ardot[N_NODES * HEADS];
__device__ int   g_deg[N_NODES];
__device__ int   g_rowptr[N_NODES + 1];
__device__ int   g_cursor[N_NODES];
__device__ int   g_esrc[N_EDGES];
__device__ float g_pool[NUM_GRAPHS * NHID];

// ---------------- tf32 helpers ----------------
__device__ __forceinline__ unsigned f2tf32(float f) {
    unsigned u;
    asm("cvt.rna.tf32.f32 %0, %1;" : "=r"(u) : "f"(f));
    return u;
}
__device__ __forceinline__ void mma_tf32(float& d0, float& d1, float& d2, float& d3,
                                         unsigned a0, unsigned a1, unsigned a2, unsigned a3,
                                         unsigned b0, unsigned b1) {
    asm("mma.sync.aligned.m16n8k8.row.col.f32.tf32.tf32.f32 "
        "{%0,%1,%2,%3}, {%4,%5,%6,%7}, {%8,%9}, {%0,%1,%2,%3};"
        : "+f"(d0), "+f"(d1), "+f"(d2), "+f"(d3)
        : "r"(a0), "r"(a1), "r"(a2), "r"(a3), "r"(b0), "r"(b1));
}

__device__ __forceinline__ float dot4(float4 a, float4 b) {
    return a.x * b.x + a.y * b.y + a.z * b.z + a.w * b.w;
}

// ---------------- CSR build ----------------
__global__ void zero_int_kernel(int* p, int n) {
    int i = blockIdx.x * blockDim.x + threadIdx.x;
    if (i < n) p[i] = 0;
}

__global__ void hist_kernel(const int* __restrict__ dst, int* __restrict__ deg, int E) {
    int i = blockIdx.x * blockDim.x + threadIdx.x;
    if (i < E) atomicAdd(&deg[dst[i]], 1);
}

__global__ void scan_kernel(const int* __restrict__ deg, int* __restrict__ rowptr,
                            int* __restrict__ cursor) {
    __shared__ int sh[1024];
    const int PER = 20;
    int tid = threadIdx.x;
    int base = tid * PER;
    int loc[PER];
    int s = 0;
    #pragma unroll
    for (int i = 0; i < PER; i++) {
        int idx = base + i;
        int v = (idx < N_NODES) ? deg[idx] : 0;
        loc[i] = s;
        s += v;
    }
    sh[tid] = s;
    __syncthreads();
    #pragma unroll
    for (int off = 1; off < 1024; off <<= 1) {
        int t = (tid >= off) ? sh[tid - off] : 0;
        __syncthreads();
        sh[tid] += t;
        __syncthreads();
    }
    int prev = (tid > 0) ? sh[tid - 1] : 0;
    #pragma unroll
    for (int i = 0; i < PER; i++) {
        int idx = base + i;
        if (idx < N_NODES) {
            int v = prev + loc[i];
            rowptr[idx] = v;
            cursor[idx] = v;
        }
    }
    if (tid == 1023) rowptr[N_NODES] = sh[1023];
}

__global__ void scatter_kernel(const int* __restrict__ src, const int* __restrict__ dst,
                               int* __restrict__ cursor, int* __restrict__ esrc, int E) {
    int i = blockIdx.x * blockDim.x + threadIdx.x;
    if (i < E) {
        int d = dst[i];
        int p = atomicAdd(&cursor[d], 1);
        esrc[p] = src[i];
    }
}

// ---------------- tf32 tensor-core GEMM, double-buffered, templated BM ----------------
// THREADS = 2*BM. Warp tile 64x32; BM=128: 8 warps (2x4); BM=64: 4 warps (1x4).
template<int BM>
__global__ __launch_bounds__(2 * BM)
void gemm_tf32_kernel(const float* __restrict__ A, const float* __restrict__ B,
                      const float* __restrict__ bias, float* __restrict__ C,
                      int M, int N, int K, float slope, int act) {
    const int BK = 16;
    const int ASTR = BM + 8;
    const int THREADS = 2 * BM;
    const int BROWS = THREADS / 16;          // B loader rows per pass
    const int BPASS = 16 / BROWS;            // 1 (BM=128) or 2 (BM=64)
    __shared__ unsigned As[2][BK * ASTR];
    __shared__ unsigned Bs[2][32 * 33 * 2];

    int tid = threadIdx.x;
    int lane = tid & 31;
    int wid = tid >> 5;
    int warpM = wid >> 2;
    int warpN = wid & 3;
    int bm = blockIdx.y * BM, bn = blockIdx.x * 128;
    int g = lane >> 2, c = lane & 3;

    float acc[4][4][4];
    #pragma unroll
    for (int mi = 0; mi < 4; mi++)
        #pragma unroll
        for (int ni = 0; ni < 4; ni++)
            #pragma unroll
            for (int r = 0; r < 4; r++) acc[mi][ni][r] = 0.f;

    int la_m = tid >> 1;
    int la_k = (tid & 1) * 8;
    int gmA = bm + la_m;
    int lbn = (tid & 15) * 8;
    int b_nb = tid & 15;

    // prefetch registers
    float4 pa0, pa1;
    float pbv[BPASS][8];

    int nT = (K + BK - 1) / BK;

    // ---- tile loader (global -> regs) ----
    auto load_tile = [&](int k0) {
        pa0 = make_float4(0.f, 0.f, 0.f, 0.f);
        pa1 = make_float4(0.f, 0.f, 0.f, 0.f);
        int gk0 = k0 + la_k;
        if (gmA < M && gk0 < K)
            pa0 = *reinterpret_cast<const float4*>(&A[(size_t)gmA * K + gk0]);
        if (gmA < M && gk0 + 4 < K)
            pa1 = *reinterpret_cast<const float4*>(&A[(size_t)gmA * K + gk0 + 4]);
        #pragma unroll
        for (int pass = 0; pass < BPASS; pass++) {
            int lbk = (tid >> 4) + pass * BROWS;
            int gk = k0 + lbk;
            float4 v0 = make_float4(0.f, 0.f, 0.f, 0.f);
            float4 v1 = make_float4(0.f, 0.f, 0.f, 0.f);
            if (gk < K) {
                v0 = *reinterpret_cast<const float4*>(&B[(size_t)gk * N + bn + lbn]);
                v1 = *reinterpret_cast<const float4*>(&B[(size_t)gk * N + bn + lbn + 4]);
            }
            pbv[pass][0] = v0.x; pbv[pass][1] = v0.y; pbv[pass][2] = v0.z; pbv[pass][3] = v0.w;
            pbv[pass][4] = v1.x; pbv[pass][5] = v1.y; pbv[pass][6] = v1.z; pbv[pass][7] = v1.w;
        }
    };
    // ---- tile store (regs -> smem, with tf32 convert) ----
    auto store_tile = [&](int buf) {
        As[buf][(la_k + 0) * ASTR + la_m] = f2tf32(pa0.x);
        As[buf][(la_k + 1) * ASTR + la_m] = f2tf32(pa0.y);
        As[buf][(la_k + 2) * ASTR + la_m] = f2tf32(pa0.z);
        As[buf][(la_k + 3) * ASTR + la_m] = f2tf32(pa0.w);
        As[buf][(la_k + 4) * ASTR + la_m] = f2tf32(pa1.x);
        As[buf][(la_k + 5) * ASTR + la_m] = f2tf32(pa1.y);
        As[buf][(la_k + 6) * ASTR + la_m] = f2tf32(pa1.z);
        As[buf][(la_k + 7) * ASTR + la_m] = f2tf32(pa1.w);
        #pragma unroll
        for (int pass = 0; pass < BPASS; pass++) {
            int lbk = (tid >> 4) + pass * BROWS;
            int b_kb = lbk >> 3;
            int b_c = lbk & 3;
            int b_half = (lbk & 7) >> 2;
            int grp = b_kb * 16 + b_nb;
            #pragma unroll
            for (int j = 0; j < 8; j++) {
                int u = grp * 33 + j * 4 + b_c;
                Bs[buf][2 * u + b_half] = f2tf32(pbv[pass][j]);
            }
        }
    };

    load_tile(0);
    store_tile(0);
    __syncthreads();

    for (int t = 0; t < nT; t++) {
        int buf = t & 1;
        bool more = (t + 1) < nT;
        if (more) load_tile((t + 1) * BK);

        #pragma unroll
        for (int kb = 0; kb < 2; kb++) {
            unsigned af[4][4];
            int r0 = (kb * 8 + c) * ASTR;
            int r1 = (kb * 8 + c + 4) * ASTR;
            #pragma unroll
            for (int mi = 0; mi < 4; mi++) {
                int m0 = warpM * 64 + mi * 16;
                af[mi][0] = As[buf][r0 + m0 + g];
                af[mi][1] = As[buf][r0 + m0 + g + 8];
                af[mi][2] = As[buf][r1 + m0 + g];
                af[mi][3] = As[buf][r1 + m0 + g + 8];
            }
            unsigned bf[4][2];
            #pragma unroll
            for (int ni = 0; ni < 4; ni++) {
                int grp = kb * 16 + warpN * 4 + ni;
                uint2 tt = *reinterpret_cast<const uint2*>(&Bs[buf][2 * (grp * 33 + lane)]);
                bf[ni][0] = tt.x;
                bf[ni][1] = tt.y;
            }
            #pragma unroll
            for (int mi = 0; mi < 4; mi++)
                #pragma unroll
                for (int ni = 0; ni < 4; ni++)
                    mma_tf32(acc[mi][ni][0], acc[mi][ni][1], acc[mi][ni][2], acc[mi][ni][3],
                             af[mi][0], af[mi][1], af[mi][2], af[mi][3],
                             bf[ni][0], bf[ni][1]);
        }

        if (more) store_tile(1 - buf);
        __syncthreads();
    }

    // ---- epilogue ----
    #pragma unroll
    for (int mi = 0; mi < 4; mi++) {
        int row0 = bm + warpM * 64 + mi * 16 + g;
        #pragma unroll
        for (int ni = 0; ni < 4; ni++) {
            int col = bn + warpN * 32 + ni * 8 + c * 2;
            float bv0 = bias ? bias[col] : 0.f;
            float bv1 = bias ? bias[col + 1] : 0.f;
            if (row0 < M) {
                float x0 = acc[mi][ni][0] + bv0;
                float x1 = acc[mi][ni][1] + bv1;
                if (act) {
                    x0 = x0 > 0.f ? x0 : slope * x0;
                    x1 = x1 > 0.f ? x1 : slope * x1;
                }
                *reinterpret_cast<float2*>(&C[(size_t)row0 * N + col]) = make_float2(x0, x1);
            }
            int row1 = row0 + 8;
            if (row1 < M) {
                float x2 = acc[mi][ni][2] + bv0;
                float x3 = acc[mi][ni][3] + bv1;
                if (act) {
                    x2 = x2 > 0.f ? x2 : slope * x2;
                    x3 = x3 > 0.f ? x3 : slope * x3;
                }
                *reinterpret_cast<float2*>(&C[(size_t)row1 * N + col]) = make_float2(x2, x3);
            }
        }
    }
}

// ---------------- precompute attention dots ----------------
template<int H>
__global__ void attdot_kernel(const float* __restrict__ feat,
                              const float* __restrict__ attL, const float* __restrict__ attR,
                              float* __restrict__ aldot, float* __restrict__ ardot) {
    int warp = (blockIdx.x * blockDim.x + threadIdx.x) >> 5;
    int lane = threadIdx.x & 31;
    if (warp >= N_NODES * H) return;
    int nid = warp / H, h = warp % H;
    float4 x = reinterpret_cast<const float4*>(feat + ((size_t)nid * H + h) * NHID)[lane];
    float4 aL = reinterpret_cast<const float4*>(attL + h * NHID)[lane];
    float4 aR = reinterpret_cast<const float4*>(attR + h * NHID)[lane];
    float al = dot4(x, aL);
    float ar = dot4(x, aR);
    #pragma unroll
    for (int o = 16; o; o >>= 1) {
        al += __shfl_xor_sync(0xffffffffu, al, o);
        ar += __shfl_xor_sync(0xffffffffu, ar, o);
    }
    if (lane == 0) { aldot[warp] = al; ardot[warp] = ar; }
}

// ---------------- SuperGAT aggregation: one warp per (node, head), 4-edge unroll ----------------
template<int H>
__global__ void agg_kernel(const float* __restrict__ feat,
                           const float* __restrict__ aldot, const float* __restrict__ ardot,
                           const float* __restrict__ bias,
                           const int* __restrict__ rowptr, const int* __restrict__ esrc,
                           float* __restrict__ out, float out_slope) {
    const int C = NHID;
    int warp = (blockIdx.x * blockDim.x + threadIdx.x) >> 5;
    int lane = threadIdx.x & 31;
    if (warp >= N_NODES * H) return;
    int nid = warp / H;
    int h   = warp % H;

    float4 xi = reinterpret_cast<const float4*>(feat + ((size_t)nid * H + h) * C)[lane];
    float ar = ardot[warp];

    float m = -INFINITY, s = 0.f;
    float4 acc = make_float4(0.f, 0.f, 0.f, 0.f);

    int e0 = rowptr[nid], e1 = rowptr[nid + 1];
    int e = e0;
    for (; e + 3 < e1; e += 4) {
        int s0 = esrc[e], s1 = esrc[e + 1], s2 = esrc[e + 2], s3 = esrc[e + 3];
        float4 xj0 = reinterpret_cast<const float4*>(feat + ((size_t)s0 * H + h) * C)[lane];
        float4 xj1 = reinterpret_cast<const float4*>(feat + ((size_t)s1 * H + h) * C)[lane];
        float4 xj2 = reinterpret_cast<const float4*>(feat + ((size_t)s2 * H + h) * C)[lane];
        float4 xj3 = reinterpret_cast<const float4*>(feat + ((size_t)s3 * H + h) * C)[lane];
        float lg0 = dot4(xi, xj0), lg1 = dot4(xi, xj1);
        float lg2 = dot4(xi, xj2), lg3 = dot4(xi, xj3);
        #pragma unroll
        for (int o = 16; o; o >>= 1) {
            lg0 += __shfl_xor_sync(0xffffffffu, lg0, o);
            lg1 += __shfl_xor_sync(0xffffffffu, lg1, o);
            lg2 += __shfl_xor_sync(0xffffffffu, lg2, o);
            lg3 += __shfl_xor_sync(0xffffffffu, lg3, o);
        }
        float a0 = (aldot[s0 * H + h] + ar) * (1.f / (1.f + __expf(-lg0)));
        float a1 = (aldot[s1 * H + h] + ar) * (1.f / (1.f + __expf(-lg1)));
        float a2 = (aldot[s2 * H + h] + ar) * (1.f / (1.f + __expf(-lg2)));
        float a3 = (aldot[s3 * H + h] + ar) * (1.f / (1.f + __expf(-lg3)));
        a0 = a0 > 0.f ? a0 : 0.2f * a0;
        a1 = a1 > 0.f ? a1 : 0.2f * a1;
        a2 = a2 > 0.f ? a2 : 0.2f * a2;
        a3 = a3 > 0.f ? a3 : 0.2f * a3;
        float mx = fmaxf(fmaxf(a0, a1), fmaxf(a2, a3));
        float mn = fmaxf(m, mx);
        float sc = __expf(m - mn);
        float w0 = __expf(a0 - mn), w1 = __expf(a1 - mn);
        float w2 = __expf(a2 - mn), w3 = __expf(a3 - mn);
        s = s * sc + w0 + w1 + w2 + w3;
        acc.x = acc.x * sc + w0 * xj0.x + w1 * xj1.x + w2 * xj2.x + w3 * xj3.x;
        acc.y = acc.y * sc + w0 * xj0.y + w1 * xj1.y + w2 * xj2.y + w3 * xj3.y;
        acc.z = acc.z * sc + w0 * xj0.z + w1 * xj1.z + w2 * xj2.z + w3 * xj3.z;
        acc.w = acc.w * sc + w0 * xj0.w + w1 * xj1.w + w2 * xj2.w + w3 * xj3.w;
        m = mn;
    }
    for (; e < e1; e++) {
        int sn = esrc[e];
        float4 xj = reinterpret_cast<const float4*>(feat + ((size_t)sn * H + h) * C)[lane];
        float lg = dot4(xi, xj);
        #pragma unroll
        for (int o = 16; o; o >>= 1) lg += __shfl_xor_sync(0xffffffffu, lg, o);
        float al = aldot[sn * H + h];
        float a = (al + ar) * (1.f / (1.f + __expf(-lg)));
        a = a > 0.f ? a : 0.2f * a;
        float mn = fmaxf(m, a);
        float sc = __expf(m - mn);
        float w = __expf(a - mn);
        s = s * sc + w;
        acc.x = acc.x * sc + w * xj.x;
        acc.y = acc.y * sc + w * xj.y;
        acc.z = acc.z * sc + w * xj.z;
        acc.w = acc.w * sc + w * xj.w;
        m = mn;
    }
    float inv = 1.f / (s + 1e-16f);
    float4 b4 = reinterpret_cast<const float4*>(bias + h * C)[lane];
    float4 r;
    r.x = acc.x * inv + b4.x; r.x = r.x > 0.f ? r.x : out_slope * r.x;
    r.y = acc.y * inv + b4.y; r.y = r.y > 0.f ? r.y : out_slope * r.y;
    r.z = acc.z * inv + b4.z; r.z = r.z > 0.f ? r.z : out_slope * r.z;
    r.w = acc.w * inv + b4.w; r.w = r.w > 0.f ? r.w : out_slope * r.w;
    reinterpret_cast<float4*>(out + ((size_t)nid * H + h) * C)[lane] = r;
}

// ---------------- graph pooling ----------------
__global__ void pool_init_kernel(float* pool) {
    int i = blockIdx.x * blockDim.x + threadIdx.x;
    if (i < NUM_GRAPHS * NHID) pool[i] = -FLT_MAX;
}

__device__ __forceinline__ void atomicMaxF(float* a, float v) {
    if (v >= 0.f) atomicMax((int*)a, __float_as_int(v));
    else          atomicMin((unsigned int*)a, __float_as_uint(v));
}

__global__ void pool_max_kernel(const float* __restrict__ x, const int* __restrict__ batch,
                                float* __restrict__ pool) {
    int i = blockIdx.x * blockDim.x + threadIdx.x;
    if (i >= N_NODES * NHID) return;
    int n = i / NHID, c = i % NHID;
    atomicMaxF(&pool[batch[n] * NHID + c], x[i]);
}

// ---------------- launch ----------------
static inline float* symf(const void* sym) {
    void* p = nullptr; cudaGetSymbolAddress(&p, sym); return (float*)p;
}
static inline int* symi(const void* sym) {
    void* p = nullptr; cudaGetSymbolAddress(&p, sym); return (int*)p;
}

extern "C" void kernel_launch(void* const* d_in, const int* in_sizes, int n_in,
                              void* d_out, int out_size) {
    const float* x      = (const float*)d_in[0];
    const int*   eidx   = (const int*)  d_in[1];
    const int*   batch  = (const int*)  d_in[2];
    const float* fc1_w  = (const float*)d_in[3];
    const float* fc1_b  = (const float*)d_in[4];
    const float* w1     = (const float*)d_in[5];
    const float* att_l1 = (const float*)d_in[6];
    const float* att_r1 = (const float*)d_in[7];
    const float* b1     = (const float*)d_in[8];
    const float* w2     = (const float*)d_in[9];
    const float* att_l2 = (const float*)d_in[10];
    const float* att_r2 = (const float*)d_in[11];
    const float* b2     = (const float*)d_in[12];
    const float* fc2_w  = (const float*)d_in[13];
    const float* fc2_b  = (const float*)d_in[14];
    float* out = (float*)d_out;

    const int* e_src = eidx;
    const int* e_dst = eidx + N_EDGES;

    float* h0 = symf(g_h0); float* f1 = symf(g_f1); float* o1 = symf(g_o1);
    float* f2 = symf(g_f2); float* o2 = symf(g_o2); float* pool = symf(g_pool);
    float* aldot = symf(g_aldot); float* ardot = symf(g_ardot);
    int* deg = symi(g_deg); int* rowptr = symi(g_rowptr);
    int* cursor = symi(g_cursor); int* esrc = symi(g_esrc);

    zero_int_kernel<<<(N_NODES + 255) / 256, 256>>>(deg, N_NODES);                     // 0
    hist_kernel<<<(N_EDGES + 255) / 256, 256>>>(e_dst, deg, N_EDGES);                  // 1

    // GEMM1: h0 = leaky(x @ fc1_w + fc1_b)  [20000,300]x[300,128] BM=64
    {
        dim3 grid(NHID / 128, (N_NODES + 63) / 64);
        gemm_tf32_kernel<64><<<grid, 128>>>(x, fc1_w, fc1_b, h0, N_NODES, NHID, N_IN, 0.01f, 1); // 2
    }
    // GEMM2: f1 = h0 @ w1   [20000,128]x[128,512]  (profiled slot 3, BM=128)
    {
        dim3 grid(HEADS * NHID / 128, (N_NODES + 127) / 128);
        gemm_tf32_kernel<128><<<grid, 256>>>(h0, w1, nullptr, f1, N_NODES, HEADS * NHID, NHID, 0.f, 0); // 3
    }

    scan_kernel<<<1, 1024>>>(deg, rowptr, cursor);                                     // 4
    scatter_kernel<<<(N_EDGES + 255) / 256, 256>>>(e_src, e_dst, cursor, esrc, N_EDGES); // 5

    {
        int warps = N_NODES * HEADS;
        attdot_kernel<HEADS><<<(warps * 32 + 255) / 256, 256>>>(f1, att_l1, att_r1, aldot, ardot); // 6
    }
    // Aggregation layer 1 (per-(node,head) warps, 4-edge unroll)
    {
        int warps = N_NODES * HEADS;
        agg_kernel<HEADS><<<(warps * 32 + 255) / 256, 256>>>(f1, aldot, ardot, b1,
                                                             rowptr, esrc, o1, 0.01f); // 7
    }
    // GEMM3: f2 = o1 @ w2   [20000,512]x[512,128] BM=64
    {
        dim3 grid(NHID / 128, (N_NODES + 63) / 64);
        gemm_tf32_kernel<64><<<grid, 128>>>(o1, w2, nullptr, f2, N_NODES, NHID, HEADS * NHID, 0.f, 0); // 8
    }
    {
        int warps = N_NODES;
        attdot_kernel<1><<<(warps * 32 + 255) / 256, 256>>>(f2, att_l2, att_r2, aldot, ardot); // 9
    }
    // Aggregation layer 2
    {
        int warps = N_NODES;
        agg_kernel<1><<<(warps * 32 + 255) / 256, 256>>>(f2, aldot, ardot, b2,
                                                         rowptr, esrc, o2, 0.01f);     // 10
    }
    pool_init_kernel<<<(NUM_GRAPHS * NHID + 255) / 256, 256>>>(pool);                  // 11
    pool_max_kernel<<<(N_NODES * NHID + 255) / 256, 256>>>(o2, batch, pool);           // 12

    // GEMM4: out = pool @ fc2_w + fc2_b   [128,128]x[128,768]  BM=128
    {
        dim3 grid(NOUT / 128, (NUM_GRAPHS + 127) / 128);
        gemm_tf32_kernel<128><<<grid, 256>>>(pool, fc2_w, fc2_b, out, NUM_GRAPHS, NOUT, NHID, 0.f, 0); // 13
    }
}